// round 16
// baseline (speedup 1.0000x reference)
#include <cuda_runtime.h>
#include <cuda_fp16.h>
#include <cstdint>

// ---------------------------------------------------------------------------
// Problem constants (fixed shapes from reference setup_inputs)
// ---------------------------------------------------------------------------
#define BB   4
#define TT   4096
#define NN   512
#define DD   1024
#define LL   768
#define HH   8
#define HD   128

// ---------------------------------------------------------------------------
// Scratch (single __device__ array; offsets in floats)
// half arrays occupy (elems/2) float slots
// ---------------------------------------------------------------------------
#define NSPLIT 8
#define OFF_XN   0LL                                 // half [B*T,D]   8388608 f
#define OFF_CN   (OFF_XN + 8388608LL)                // half [B*N,L]    786432 f
#define OFF_K    (OFF_CN + 786432LL)                 // half [B*N,D]   1048576 f
#define OFF_V    (OFF_K  + 1048576LL)                // half [B*N,D]   1048576 f
#define OFF_KM   (OFF_V  + 1048576LL)                // f32  [B,D]
#define OFF_KS   (OFF_KM + 4096LL)                   // f32  [B,D]
#define OFF_CP   (OFF_KS + 4096LL)                   // half [NSPLIT,B*H,128,128] 2097152 f
#define OFF_CTX  (OFF_CP + 2097152LL)                // half [B*H,dk,dv] 262144 f
#define OFF_WQ16 (OFF_CTX + 262144LL)                // half [1024,1024] 524288 f
#define OFF_WK16 (OFF_WQ16 + 524288LL)               // half [768,1024]  393216 f
#define OFF_WV16 (OFF_WK16 + 393216LL)               // half [768,1024]  393216 f
#define SCRATCH_TOTAL (OFF_WV16 + 393216LL)

__device__ __align__(256) float g_buf[SCRATCH_TOTAL];

// ---------------------------------------------------------------------------
// Helpers
// ---------------------------------------------------------------------------
__device__ __forceinline__ void mma_fp16(float* c, const uint32_t* a, const uint32_t* b) {
    asm volatile(
        "mma.sync.aligned.m16n8k16.row.col.f32.f16.f16.f32 "
        "{%0,%1,%2,%3}, {%4,%5,%6,%7}, {%8,%9}, {%0,%1,%2,%3};\n"
        : "+f"(c[0]), "+f"(c[1]), "+f"(c[2]), "+f"(c[3])
        : "r"(a[0]), "r"(a[1]), "r"(a[2]), "r"(a[3]),
          "r"(b[0]), "r"(b[1]));
}

__device__ __forceinline__ void ldsm4(uint32_t& r0, uint32_t& r1, uint32_t& r2,
                                      uint32_t& r3, uint32_t addr) {
    asm volatile("ldmatrix.sync.aligned.m8n8.x4.shared.b16 {%0,%1,%2,%3}, [%4];\n"
                 : "=r"(r0), "=r"(r1), "=r"(r2), "=r"(r3) : "r"(addr));
}

__device__ __forceinline__ void ldsm4t(uint32_t& r0, uint32_t& r1, uint32_t& r2,
                                       uint32_t& r3, uint32_t addr) {
    asm volatile("ldmatrix.sync.aligned.m8n8.x4.trans.shared.b16 {%0,%1,%2,%3}, [%4];\n"
                 : "=r"(r0), "=r"(r1), "=r"(r2), "=r"(r3) : "r"(addr));
}

__device__ __forceinline__ void cp16(void* s, const void* g) {
    uint32_t sa = (uint32_t)__cvta_generic_to_shared(s);
    asm volatile("cp.async.cg.shared.global [%0], [%1], 16;\n" :: "r"(sa), "l"(g));
}

// ---------------------------------------------------------------------------
// Convert weights f32 -> f16 (layout kept [K, N])
// ---------------------------------------------------------------------------
__global__ void conv_weights(const float* __restrict__ wq, const float* __restrict__ wk,
                             const float* __restrict__ wv, __half* __restrict__ out) {
    const size_t fi = ((size_t)blockIdx.x * 256 + threadIdx.x) * 4;
    const float* src;
    size_t off;
    if (fi < 1048576) { src = wq; off = fi; }
    else if (fi < 1048576 + 786432) { src = wk; off = fi - 1048576; }
    else { src = wv; off = fi - (1048576 + 786432); }
    float4 v = *(const float4*)(src + off);
    *(half2*)(out + fi) = __floats2half2_rn(v.x, v.y);
    *(half2*)(out + fi + 2) = __floats2half2_rn(v.z, v.w);
}

// ---------------------------------------------------------------------------
// LayerNorm D=1024, vectorized
// ---------------------------------------------------------------------------
__global__ void ln1024(const float* __restrict__ x, const float* __restrict__ g,
                       const float* __restrict__ bta, __half* __restrict__ out) {
    const size_t row = blockIdx.x;
    const int c = threadIdx.x * 4;
    const float4 v = *(const float4*)(x + row * DD + c);
    float s = v.x + v.y + v.z + v.w;
    float sq = v.x * v.x + v.y * v.y + v.z * v.z + v.w * v.w;
#pragma unroll
    for (int o = 16; o; o >>= 1) {
        s += __shfl_xor_sync(0xffffffffu, s, o);
        sq += __shfl_xor_sync(0xffffffffu, sq, o);
    }
    __shared__ float sm[8], sv[8];
    const int w = threadIdx.x >> 5;
    if ((threadIdx.x & 31) == 0) { sm[w] = s; sv[w] = sq; }
    __syncthreads();
    if (threadIdx.x < 32) {
        s = (threadIdx.x < 8) ? sm[threadIdx.x] : 0.f;
        sq = (threadIdx.x < 8) ? sv[threadIdx.x] : 0.f;
#pragma unroll
        for (int o = 4; o; o >>= 1) {
            s += __shfl_xor_sync(0xffffffffu, s, o);
            sq += __shfl_xor_sync(0xffffffffu, sq, o);
        }
        if (threadIdx.x == 0) { sm[0] = s; sv[0] = sq; }
    }
    __syncthreads();
    const float mean = sm[0] * (1.f / DD);
    const float rstd = rsqrtf(sv[0] * (1.f / DD) - mean * mean + 1e-5f);
    const float4 g4 = *(const float4*)(g + c);
    const float4 b4 = *(const float4*)(bta + c);
    half2 h0 = __floats2half2_rn((v.x - mean) * rstd * g4.x + b4.x,
                                 (v.y - mean) * rstd * g4.y + b4.y);
    half2 h1 = __floats2half2_rn((v.z - mean) * rstd * g4.z + b4.z,
                                 (v.w - mean) * rstd * g4.w + b4.w);
    *(half2*)(out + row * DD + c) = h0;
    *(half2*)(out + row * DD + c + 2) = h1;
}

// ---------------------------------------------------------------------------
// LayerNorm generic (cond path, L=768)
// ---------------------------------------------------------------------------
template <int DIM>
__global__ void ln_kernel(const float* __restrict__ x, const float* __restrict__ g,
                          const float* __restrict__ bta, __half* __restrict__ out) {
    constexpr int PER = DIM / 256;
    const size_t row = blockIdx.x;
    const float* xr = x + row * DIM;
    float v[PER];
    float s = 0.f, sq = 0.f;
#pragma unroll
    for (int i = 0; i < PER; i++) {
        v[i] = xr[threadIdx.x + 256 * i];
        s += v[i];
        sq += v[i] * v[i];
    }
#pragma unroll
    for (int o = 16; o; o >>= 1) {
        s += __shfl_xor_sync(0xffffffffu, s, o);
        sq += __shfl_xor_sync(0xffffffffu, sq, o);
    }
    __shared__ float sm[8], sv[8];
    int w = threadIdx.x >> 5;
    if ((threadIdx.x & 31) == 0) { sm[w] = s; sv[w] = sq; }
    __syncthreads();
    if (threadIdx.x < 32) {
        s = (threadIdx.x < 8) ? sm[threadIdx.x] : 0.f;
        sq = (threadIdx.x < 8) ? sv[threadIdx.x] : 0.f;
#pragma unroll
        for (int o = 4; o; o >>= 1) {
            s += __shfl_xor_sync(0xffffffffu, s, o);
            sq += __shfl_xor_sync(0xffffffffu, sq, o);
        }
        if (threadIdx.x == 0) { sm[0] = s; sv[0] = sq; }
    }
    __syncthreads();
    const float mean = sm[0] * (1.f / DIM);
    const float var = sv[0] * (1.f / DIM) - mean * mean;
    const float rstd = rsqrtf(var + 1e-5f);
    __half* orow = out + row * DIM;
#pragma unroll
    for (int i = 0; i < PER; i++) {
        int c = threadIdx.x + 256 * i;
        orow[c] = __float2half_rn((v[i] - mean) * rstd * g[c] + bta[c]);
    }
}

// ---------------------------------------------------------------------------
// fp16 tensor-core GEMM: 128x128 tile, BK=64, cp.async 3-stage, f32 accum.
// 8 warps (2m x 4n), warp tile 64x32.  (R11/R12 proven config)
// FUSE_PV: tile == one (b,head): row softmax -> P(fp16, smem) -> P @ ctx -> y.
// OutT = __half: epilogue writes fp16 (kv path); OutT = float: f32 (y path).
// Dual (Bm2!=null): grid.x split between {Bm,bias,C} and {Bm2,bias2,C2}.
// ---------------------------------------------------------------------------
#define STAGES 3
#define AS_H 72              // halves per A smem row (64 + 8 pad)
#define BS_H 136             // halves per B smem row (128 + 8 pad)
#define A_ST_H (128 * AS_H)
#define B_ST_H (64 * BS_H)
#define SMEM_BYTES (STAGES * (A_ST_H + B_ST_H) * 2)   // 107520
#define P_OFF   8192
#define CTX_OFF (P_OFF + 128 * BS_H * 2)              // 43008
#define RED_OFF (CTX_OFF + 128 * BS_H * 2)            // 77824

template <bool FUSE_PV, typename OutT>
__global__ void __launch_bounds__(256, 2)
gemm_fp16(const __half* __restrict__ A, const __half* __restrict__ Bm,
          const float* __restrict__ bias, OutT* __restrict__ C,
          const __half* __restrict__ Bm2, const float* __restrict__ bias2,
          OutT* __restrict__ C2, const __half* __restrict__ ctxg,
          int K, int lda, int ldb, int ldc) {
    extern __shared__ __align__(16) char smraw[];
    __half* Asm = (__half*)smraw;
    __half* Bsm = Asm + STAGES * A_ST_H;

    int tN;
    if (Bm2 != nullptr) {
        const int half_g = gridDim.x >> 1;
        if (blockIdx.x >= half_g) {
            Bm = Bm2; bias = bias2; C = C2;
            tN = (blockIdx.x - half_g) * 128;
        } else {
            tN = blockIdx.x * 128;
        }
    } else {
        tN = blockIdx.x * 128;
    }
    const int tM = blockIdx.y * 128;
    const int tid = threadIdx.x;
    const int lane = tid & 31, warp = tid >> 5;
    const int m_base = (warp & 1) * 64;
    const int n_base = (warp >> 1) * 32;

    const __half* Ag = A + (size_t)tM * lda;
    const __half* Bg = Bm + tN;
    const int nk = K >> 6;   // BK = 64

    auto issue = [&](int kt) {
        const int st = kt % STAGES;
        __half* Al = Asm + st * A_ST_H;
        __half* Bl = Bsm + st * B_ST_H;
        const int k0 = kt << 6;
#pragma unroll
        for (int j = 0; j < 4; j++) {
            const int ci = tid + 256 * j;
            const int r = ci >> 3, c = (ci & 7) * 8;
            cp16(Al + r * AS_H + c, Ag + (size_t)r * lda + k0 + c);
        }
#pragma unroll
        for (int j = 0; j < 4; j++) {
            const int ci = tid + 256 * j;
            const int r = ci >> 4, c = (ci & 15) * 8;
            cp16(Bl + r * BS_H + c, Bg + (size_t)(k0 + r) * ldb + c);
        }
    };

    const uint32_t asm_u32 = (uint32_t)__cvta_generic_to_shared(Asm);
    const uint32_t bsm_u32 = (uint32_t)__cvta_generic_to_shared(Bsm);
    const uint32_t a_lane = (uint32_t)(((lane & 15) * AS_H + (lane >> 4) * 8) * 2);
    const uint32_t b_lane = (uint32_t)(((lane & 15) * BS_H + (lane >> 4) * 8) * 2);

    float acc[4][4][4];
#pragma unroll
    for (int i = 0; i < 4; i++)
#pragma unroll
        for (int j = 0; j < 4; j++)
#pragma unroll
            for (int r = 0; r < 4; r++) acc[i][j][r] = 0.f;

    issue(0);
    asm volatile("cp.async.commit_group;\n");
    issue(1);
    asm volatile("cp.async.commit_group;\n");

    for (int kt = 0; kt < nk; kt++) {
        asm volatile("cp.async.wait_group %0;\n" :: "n"(1));
        __syncthreads();
        if (kt + 2 < nk) issue(kt + 2);
        asm volatile("cp.async.commit_group;\n");

        const int st = kt % STAGES;
        const uint32_t a_st = asm_u32 + (uint32_t)(st * A_ST_H * 2) + a_lane;
        const uint32_t b_st = bsm_u32 + (uint32_t)(st * B_ST_H * 2) + b_lane;
#pragma unroll
        for (int kk = 0; kk < 4; kk++) {
            uint32_t af[4][4];
#pragma unroll
            for (int im = 0; im < 4; im++)
                ldsm4(af[im][0], af[im][1], af[im][2], af[im][3],
                      a_st + (uint32_t)(((m_base + im * 16) * AS_H + kk * 16) * 2));
            uint32_t bf[2][4];
#pragma unroll
            for (int t = 0; t < 2; t++)
                ldsm4t(bf[t][0], bf[t][1], bf[t][2], bf[t][3],
                       b_st + (uint32_t)((kk * 16 * BS_H + n_base + t * 16) * 2));
#pragma unroll
            for (int im = 0; im < 4; im++)
#pragma unroll
                for (int in = 0; in < 4; in++)
                    mma_fp16(acc[im][in], af[im], &bf[in >> 1][(in & 1) * 2]);
        }
    }
    __syncthreads();   // mainloop smem dead; epilogue may reuse

    // -------- bias --------
    float b0[4], b1[4];
#pragma unroll
    for (int in = 0; in < 4; in++) {
        if (bias != nullptr) {
            const int c = tN + n_base + in * 8 + 2 * (lane & 3);
            b0[in] = __ldg(bias + c);
            b1[in] = __ldg(bias + c + 1);
        } else { b0[in] = 0.f; b1[in] = 0.f; }
    }
#pragma unroll
    for (int im = 0; im < 4; im++)
#pragma unroll
        for (int in = 0; in < 4; in++) {
            acc[im][in][0] += b0[in];
            acc[im][in][1] += b1[in];
            acc[im][in][2] += b0[in];
            acc[im][in][3] += b1[in];
        }

    if (FUSE_PV) {
        // ---- start ctx loads (overlap with softmax math) ----
        __half* Psm = (__half*)(smraw + P_OFF);
        __half* Csm = (__half*)(smraw + CTX_OFF);
        float* red = (float*)(smraw + RED_OFF);
        float* red2 = red + 512;
        const int bh = (tM >> 12) * HH + blockIdx.x;
        const __half* cg = ctxg + ((size_t)bh << 14);
#pragma unroll
        for (int j = 0; j < 8; j++) {
            const int ci = tid + 256 * j;
            const int r = ci >> 4, c = (ci & 15) * 8;
            cp16(Csm + r * BS_H + c, cg + (size_t)r * HD + c);
        }
        asm volatile("cp.async.commit_group;\n");

        const int wn = warp >> 1;
        float m0[4], m1[4];
#pragma unroll
        for (int im = 0; im < 4; im++) {
            float a = -1e30f, b = -1e30f;
#pragma unroll
            for (int in = 0; in < 4; in++) {
                a = fmaxf(a, fmaxf(acc[im][in][0], acc[im][in][1]));
                b = fmaxf(b, fmaxf(acc[im][in][2], acc[im][in][3]));
            }
            a = fmaxf(a, __shfl_xor_sync(0xffffffffu, a, 1));
            a = fmaxf(a, __shfl_xor_sync(0xffffffffu, a, 2));
            b = fmaxf(b, __shfl_xor_sync(0xffffffffu, b, 1));
            b = fmaxf(b, __shfl_xor_sync(0xffffffffu, b, 2));
            m0[im] = a; m1[im] = b;
        }
        if ((lane & 3) == 0) {
#pragma unroll
            for (int im = 0; im < 4; im++) {
                const int r = m_base + im * 16 + (lane >> 2);
                red[r * 4 + wn] = m0[im];
                red[(r + 8) * 4 + wn] = m1[im];
            }
        }
        __syncthreads();
        float M0[4], M1[4];
#pragma unroll
        for (int im = 0; im < 4; im++) {
            const int r = m_base + im * 16 + (lane >> 2);
            M0[im] = fmaxf(fmaxf(red[r * 4], red[r * 4 + 1]),
                           fmaxf(red[r * 4 + 2], red[r * 4 + 3]));
            M1[im] = fmaxf(fmaxf(red[(r + 8) * 4], red[(r + 8) * 4 + 1]),
                           fmaxf(red[(r + 8) * 4 + 2], red[(r + 8) * 4 + 3]));
        }
        float s0[4], s1[4];
#pragma unroll
        for (int im = 0; im < 4; im++) {
            float sa = 0.f, sb = 0.f;
#pragma unroll
            for (int in = 0; in < 4; in++) {
                acc[im][in][0] = __expf(acc[im][in][0] - M0[im]);
                acc[im][in][1] = __expf(acc[im][in][1] - M0[im]);
                acc[im][in][2] = __expf(acc[im][in][2] - M1[im]);
                acc[im][in][3] = __expf(acc[im][in][3] - M1[im]);
                sa += acc[im][in][0] + acc[im][in][1];
                sb += acc[im][in][2] + acc[im][in][3];
            }
            sa += __shfl_xor_sync(0xffffffffu, sa, 1);
            sa += __shfl_xor_sync(0xffffffffu, sa, 2);
            sb += __shfl_xor_sync(0xffffffffu, sb, 1);
            sb += __shfl_xor_sync(0xffffffffu, sb, 2);
            s0[im] = sa; s1[im] = sb;
        }
        if ((lane & 3) == 0) {
#pragma unroll
            for (int im = 0; im < 4; im++) {
                const int r = m_base + im * 16 + (lane >> 2);
                red2[r * 4 + wn] = s0[im];
                red2[(r + 8) * 4 + wn] = s1[im];
            }
        }
        __syncthreads();
#pragma unroll
        for (int im = 0; im < 4; im++) {
            const int r = m_base + im * 16 + (lane >> 2);
            const float inv0 = 1.f / (red2[r * 4] + red2[r * 4 + 1] +
                                      red2[r * 4 + 2] + red2[r * 4 + 3]);
            const float inv1 = 1.f / (red2[(r + 8) * 4] + red2[(r + 8) * 4 + 1] +
                                      red2[(r + 8) * 4 + 2] + red2[(r + 8) * 4 + 3]);
#pragma unroll
            for (int in = 0; in < 4; in++) {
                const int c = n_base + in * 8 + 2 * (lane & 3);
                *(half2*)(Psm + (size_t)r * BS_H + c) =
                    __floats2half2_rn(acc[im][in][0] * inv0, acc[im][in][1] * inv0);
                *(half2*)(Psm + (size_t)(r + 8) * BS_H + c) =
                    __floats2half2_rn(acc[im][in][2] * inv1, acc[im][in][3] * inv1);
            }
        }
        asm volatile("cp.async.wait_group 0;\n");
        __syncthreads();

        float ac2[4][4][4];
#pragma unroll
        for (int i = 0; i < 4; i++)
#pragma unroll
            for (int j = 0; j < 4; j++)
#pragma unroll
                for (int r = 0; r < 4; r++) ac2[i][j][r] = 0.f;

        const uint32_t p_u32 = (uint32_t)__cvta_generic_to_shared(Psm) + b_lane;
        const uint32_t c_u32 = (uint32_t)__cvta_generic_to_shared(Csm) + b_lane;
#pragma unroll
        for (int kk = 0; kk < 8; kk++) {
            uint32_t af[4][4];
#pragma unroll
            for (int im = 0; im < 4; im++)
                ldsm4(af[im][0], af[im][1], af[im][2], af[im][3],
                      p_u32 + (uint32_t)(((m_base + im * 16) * BS_H + kk * 16) * 2));
            uint32_t bf[2][4];
#pragma unroll
            for (int t = 0; t < 2; t++)
                ldsm4t(bf[t][0], bf[t][1], bf[t][2], bf[t][3],
                       c_u32 + (uint32_t)((kk * 16 * BS_H + n_base + t * 16) * 2));
#pragma unroll
            for (int im = 0; im < 4; im++)
#pragma unroll
                for (int in = 0; in < 4; in++)
                    mma_fp16(ac2[im][in], af[im], &bf[in >> 1][(in & 1) * 2]);
        }
#pragma unroll
        for (int im = 0; im < 4; im++) {
            const int r0 = tM + m_base + im * 16 + (lane >> 2);
#pragma unroll
            for (int in = 0; in < 4; in++) {
                const int c = tN + n_base + in * 8 + 2 * (lane & 3);
                *(float2*)((float*)C + (size_t)r0 * ldc + c) =
                    make_float2(ac2[im][in][0], ac2[im][in][1]);
                *(float2*)((float*)C + (size_t)(r0 + 8) * ldc + c) =
                    make_float2(ac2[im][in][2], ac2[im][in][3]);
            }
        }
    } else {
#pragma unroll
        for (int im = 0; im < 4; im++) {
            const int r0 = tM + m_base + im * 16 + (lane >> 2);
#pragma unroll
            for (int in = 0; in < 4; in++) {
                const int c = tN + n_base + in * 8 + 2 * (lane & 3);
                if constexpr (sizeof(OutT) == 2) {
                    *(half2*)((__half*)C + (size_t)r0 * ldc + c) =
                        __floats2half2_rn(acc[im][in][0], acc[im][in][1]);
                    *(half2*)((__half*)C + (size_t)(r0 + 8) * ldc + c) =
                        __floats2half2_rn(acc[im][in][2], acc[im][in][3]);
                } else {
                    *(float2*)((float*)C + (size_t)r0 * ldc + c) =
                        make_float2(acc[im][in][0], acc[im][in][1]);
                    *(float2*)((float*)C + (size_t)(r0 + 8) * ldc + c) =
                        make_float2(acc[im][in][2], acc[im][in][3]);
                }
            }
        }
    }
}

// ---------------------------------------------------------------------------
// k column softmax stats — single pass on fp16 k, rescaled partials.
// ---------------------------------------------------------------------------
__global__ void __launch_bounds__(512)
kcol_stats(const __half* __restrict__ k, float* __restrict__ om,
           float* __restrict__ os) {
    const int b = blockIdx.x >> 5;
    const int cg = blockIdx.x & 31;
    const int cl = threadIdx.x & 31;
    const int chunk = threadIdx.x >> 5;          // 0..15
    const int col = cg * 32 + cl;
    const __half* p = k + (size_t)b * NN * DD + (size_t)(chunk * 32) * DD + col;

    float v[32];
    float m = -1e30f;
#pragma unroll
    for (int i = 0; i < 32; i++) {
        v[i] = __half2float(p[(size_t)i * DD]);
        m = fmaxf(m, v[i]);
    }
    float s = 0.f;
#pragma unroll
    for (int i = 0; i < 32; i++) s += __expf(v[i] - m);

    __shared__ float sm[16][32], ss[16][32];
    sm[chunk][cl] = m;
    ss[chunk][cl] = s;
    __syncthreads();
    if (chunk == 0) {
        float M = sm[0][cl];
#pragma unroll
        for (int i = 1; i < 16; i++) M = fmaxf(M, sm[i][cl]);
        float S = 0.f;
#pragma unroll
        for (int i = 0; i < 16; i++) S += ss[i][cl] * __expf(sm[i][cl] - M);
        om[b * DD + col] = M;
        os[b * DD + col] = S;
    }
}

// ---------------------------------------------------------------------------
// context partials via fp16 MMA (one CTA per (bh, 64-token split)),
// fp16 k/v inputs (half2 loads), fp16 partial output.
// ---------------------------------------------------------------------------
__global__ void __launch_bounds__(256)
context_mma(const __half* __restrict__ k, const __half* __restrict__ v,
            const float* __restrict__ km, const float* __restrict__ ks,
            __half* __restrict__ cp) {
    const int bh = blockIdx.x;
    const int b = bh >> 3, h = bh & 7;
    const int n0 = blockIdx.y * 64;
    __shared__ __half Ek[64 * BS_H], Vs[64 * BS_H];

    const __half* kb = k + (size_t)b * NN * DD + h * HD;
    const __half* vb = v + (size_t)b * NN * DD + h * HD;
    const float* kmb = km + b * DD + h * HD;
    const float* ksb = ks + b * DD + h * HD;

    const int tid = threadIdx.x;
    const int lane = tid & 31, warp = tid >> 5;
    const int m_base = (warp & 1) * 64;
    const int n_base = (warp >> 1) * 32;

    // 64 rows x 64 half2 cols
    for (int t = tid; t < 64 * 64; t += 256) {
        const int r = t >> 6, c = (t & 63) * 2;
        const size_t gi = (size_t)(n0 + r) * DD + c;
        half2 kh = *(const half2*)(kb + gi);
        half2 vh = *(const half2*)(vb + gi);
        *(half2*)(Ek + r * BS_H + c) = __floats2half2_rn(
            __expf(__half2float(kh.x) - kmb[c]),
            __expf(__half2float(kh.y) - kmb[c + 1]));
        *(half2*)(Vs + r * BS_H + c) = vh;
    }
    __syncthreads();

    float acc[4][4][4];
#pragma unroll
    for (int i = 0; i < 4; i++)
#pragma unroll
        for (int j = 0; j < 4; j++)
#pragma unroll
            for (int r = 0; r < 4; r++) acc[i][j][r] = 0.f;

    const uint32_t lane_off = (uint32_t)(((lane & 15) * BS_H + (lane >> 4) * 8) * 2);
    const uint32_t e_u32 = (uint32_t)__cvta_generic_to_shared(Ek) + lane_off;
    const uint32_t v_u32 = (uint32_t)__cvta_generic_to_shared(Vs) + lane_off;
#pragma unroll
    for (int kk = 0; kk < 4; kk++) {
        uint32_t af[4][4];
#pragma unroll
        for (int im = 0; im < 4; im++) {
            uint32_t r0, r1, r2, r3;
            ldsm4t(r0, r1, r2, r3,
                   e_u32 + (uint32_t)((kk * 16 * BS_H + m_base + im * 16) * 2));
            af[im][0] = r0; af[im][1] = r2; af[im][2] = r1; af[im][3] = r3;
        }
        uint32_t bf[2][4];
#pragma unroll
        for (int t = 0; t < 2; t++)
            ldsm4t(bf[t][0], bf[t][1], bf[t][2], bf[t][3],
                   v_u32 + (uint32_t)((kk * 16 * BS_H + n_base + t * 16) * 2));
#pragma unroll
        for (int im = 0; im < 4; im++)
#pragma unroll
            for (int in = 0; in < 4; in++)
                mma_fp16(acc[im][in], af[im], &bf[in >> 1][(in & 1) * 2]);
    }

    __half* out = cp + ((size_t)blockIdx.y * 32 + bh) * (HD * HD);
#pragma unroll
    for (int im = 0; im < 4; im++) {
        const int r = m_base + im * 16 + (lane >> 2);
        const float rs0 = 1.f / ksb[r];
        const float rs1 = 1.f / ksb[r + 8];
#pragma unroll
        for (int in = 0; in < 4; in++) {
            const int c = n_base + in * 8 + 2 * (lane & 3);
            *(half2*)(out + (size_t)r * HD + c) =
                __floats2half2_rn(acc[im][in][0] * rs0, acc[im][in][1] * rs0);
            *(half2*)(out + (size_t)(r + 8) * HD + c) =
                __floats2half2_rn(acc[im][in][2] * rs1, acc[im][in][3] * rs1);
        }
    }
}

// sum NSPLIT fp16 partials (f32 accumulate); fp16 output [bh][dk][dv]
__global__ void ctx_reduce(const __half* __restrict__ cp, __half* __restrict__ ctx) {
    const size_t i = (size_t)blockIdx.x * 256 + threadIdx.x;
    float s = 0.f;
#pragma unroll
    for (int p = 0; p < NSPLIT; p++)
        s += __half2float(cp[i + (size_t)p * 524288]);
    ctx[i] = __float2half_rn(s);
}

// ---------------------------------------------------------------------------
// Launch
// ---------------------------------------------------------------------------
extern "C" void kernel_launch(void* const* d_in, const int* in_sizes, int n_in,
                              void* d_out, int out_size) {
    const float* x     = (const float*)d_in[0];
    const float* cond  = (const float*)d_in[1];
    const float* ln_g  = (const float*)d_in[2];
    const float* ln_b  = (const float*)d_in[3];
    const float* tln_g = (const float*)d_in[4];
    const float* tln_b = (const float*)d_in[5];
    const float* Wq    = (const float*)d_in[6];
    const float* bq    = (const float*)d_in[7];
    const float* Wk    = (const float*)d_in[8];
    const float* bk    = (const float*)d_in[9];
    const float* Wv    = (const float*)d_in[10];
    const float* bv    = (const float*)d_in[11];
    float* y = (float*)d_out;

    float* base = nullptr;
    cudaGetSymbolAddress((void**)&base, g_buf);
    __half* xn   = (__half*)(base + OFF_XN);
    __half* cn   = (__half*)(base + OFF_CN);
    __half* kk   = (__half*)(base + OFF_K);
    __half* vv   = (__half*)(base + OFF_V);
    float*  km   = base + OFF_KM;
    float*  ks   = base + OFF_KS;
    __half* cp   = (__half*)(base + OFF_CP);
    __half* ctx  = (__half*)(base + OFF_CTX);
    __half* wq16 = (__half*)(base + OFF_WQ16);
    __half* wk16 = (__half*)(base + OFF_WK16);
    __half* wv16 = (__half*)(base + OFF_WV16);

    cudaFuncSetAttribute(gemm_fp16<true, float>,
                         cudaFuncAttributeMaxDynamicSharedMemorySize, SMEM_BYTES);
    cudaFuncSetAttribute(gemm_fp16<false, __half>,
                         cudaFuncAttributeMaxDynamicSharedMemorySize, SMEM_BYTES);

    // 0: convert weights to fp16; LN(cond)
    conv_weights<<<2560, 256>>>(Wq, Wk, Wv, wq16);
    ln_kernel<LL><<<BB * NN, 256>>>(cond, tln_g, tln_b, cn);

    // 1: k,v = cn @ W{k,v} + b fused in one launch (fp16 outputs)
    gemm_fp16<false, __half><<<dim3(2 * DD / 128, (BB * NN) / 128, 1), 256, SMEM_BYTES>>>(
        cn, wk16, bk, kk, wv16, bv, vv, nullptr,
        LL, LL, DD, DD);

    // 2: k column softmax stats (single pass on fp16 k)
    kcol_stats<<<BB * 32, 512>>>(kk, km, ks);

    // 3-4: context = softmax_N(k)^T @ v  (8-way split, fp16 MMA + fp16 partials)
    context_mma<<<dim3(BB * HH, NSPLIT), 256>>>(kk, vv, km, ks, cp);
    ctx_reduce<<<(BB * HH * HD * HD) / 256, 256>>>(cp, ctx);

    // 5: LN(x) (vectorized, fp16 output)
    ln1024<<<BB * TT, 256>>>(x, ln_g, ln_b, xn);

    // 6: FUSED: q = softmax_head(xn @ Wq + bq); y = q @ ctx  -> d_out (f32)
    gemm_fp16<true, float><<<dim3(DD / 128, (BB * TT) / 128, 1), 256, SMEM_BYTES>>>(
        xn, wq16, bq, y, nullptr, nullptr, nullptr, ctx,
        DD, DD, DD, DD);
}

// round 17
// speedup vs baseline: 1.0252x; 1.0252x over previous
#include <cuda_runtime.h>
#include <cuda_fp16.h>
#include <cstdint>

// ---------------------------------------------------------------------------
// Problem constants (fixed shapes from reference setup_inputs)
// ---------------------------------------------------------------------------
#define BB   4
#define TT   4096
#define NN   512
#define DD   1024
#define LL   768
#define HH   8
#define HD   128

// ---------------------------------------------------------------------------
// Scratch (single __device__ array; offsets in floats)
// half arrays occupy (elems/2) float slots
// ---------------------------------------------------------------------------
#define NSPLIT 8
#define OFF_XN   0LL                                 // half [B*T,D]   8388608 f
#define OFF_CN   (OFF_XN + 8388608LL)                // half [B*N,L]    786432 f
#define OFF_K    (OFF_CN + 786432LL)                 // half [B*N,D]   1048576 f
#define OFF_V    (OFF_K  + 1048576LL)                // half [B*N,D]   1048576 f
#define OFF_PM   (OFF_V  + 1048576LL)                // f32 [NSPLIT,32,128] 32768 f
#define OFF_PS   (OFF_PM + 32768LL)                  // f32 [NSPLIT,32,128] 32768 f
#define OFF_CP   (OFF_PS + 32768LL)                  // half [NSPLIT,32,128,128] 2097152 f
#define OFF_CTX  (OFF_CP + 2097152LL)                // half [B*H,dk,dv] 262144 f
#define OFF_WQ16 (OFF_CTX + 262144LL)                // half [1024,1024] 524288 f
#define OFF_WK16 (OFF_WQ16 + 524288LL)               // half [768,1024]  393216 f
#define OFF_WV16 (OFF_WK16 + 393216LL)               // half [768,1024]  393216 f
#define SCRATCH_TOTAL (OFF_WV16 + 393216LL)

__device__ __align__(256) float g_buf[SCRATCH_TOTAL];

// ---------------------------------------------------------------------------
// Helpers
// ---------------------------------------------------------------------------
__device__ __forceinline__ void mma_fp16(float* c, const uint32_t* a, const uint32_t* b) {
    asm volatile(
        "mma.sync.aligned.m16n8k16.row.col.f32.f16.f16.f32 "
        "{%0,%1,%2,%3}, {%4,%5,%6,%7}, {%8,%9}, {%0,%1,%2,%3};\n"
        : "+f"(c[0]), "+f"(c[1]), "+f"(c[2]), "+f"(c[3])
        : "r"(a[0]), "r"(a[1]), "r"(a[2]), "r"(a[3]),
          "r"(b[0]), "r"(b[1]));
}

__device__ __forceinline__ void ldsm4(uint32_t& r0, uint32_t& r1, uint32_t& r2,
                                      uint32_t& r3, uint32_t addr) {
    asm volatile("ldmatrix.sync.aligned.m8n8.x4.shared.b16 {%0,%1,%2,%3}, [%4];\n"
                 : "=r"(r0), "=r"(r1), "=r"(r2), "=r"(r3) : "r"(addr));
}

__device__ __forceinline__ void ldsm4t(uint32_t& r0, uint32_t& r1, uint32_t& r2,
                                       uint32_t& r3, uint32_t addr) {
    asm volatile("ldmatrix.sync.aligned.m8n8.x4.trans.shared.b16 {%0,%1,%2,%3}, [%4];\n"
                 : "=r"(r0), "=r"(r1), "=r"(r2), "=r"(r3) : "r"(addr));
}

__device__ __forceinline__ void cp16(void* s, const void* g) {
    uint32_t sa = (uint32_t)__cvta_generic_to_shared(s);
    asm volatile("cp.async.cg.shared.global [%0], [%1], 16;\n" :: "r"(sa), "l"(g));
}

// ---------------------------------------------------------------------------
// Convert weights f32 -> f16 (layout kept [K, N])
// ---------------------------------------------------------------------------
__global__ void conv_weights(const float* __restrict__ wq, const float* __restrict__ wk,
                             const float* __restrict__ wv, __half* __restrict__ out) {
    const size_t fi = ((size_t)blockIdx.x * 256 + threadIdx.x) * 4;
    const float* src;
    size_t off;
    if (fi < 1048576) { src = wq; off = fi; }
    else if (fi < 1048576 + 786432) { src = wk; off = fi - 1048576; }
    else { src = wv; off = fi - (1048576 + 786432); }
    float4 v = *(const float4*)(src + off);
    *(half2*)(out + fi) = __floats2half2_rn(v.x, v.y);
    *(half2*)(out + fi + 2) = __floats2half2_rn(v.z, v.w);
}

// ---------------------------------------------------------------------------
// LayerNorm D=1024, vectorized
// ---------------------------------------------------------------------------
__global__ void ln1024(const float* __restrict__ x, const float* __restrict__ g,
                       const float* __restrict__ bta, __half* __restrict__ out) {
    const size_t row = blockIdx.x;
    const int c = threadIdx.x * 4;
    const float4 v = *(const float4*)(x + row * DD + c);
    float s = v.x + v.y + v.z + v.w;
    float sq = v.x * v.x + v.y * v.y + v.z * v.z + v.w * v.w;
#pragma unroll
    for (int o = 16; o; o >>= 1) {
        s += __shfl_xor_sync(0xffffffffu, s, o);
        sq += __shfl_xor_sync(0xffffffffu, sq, o);
    }
    __shared__ float sm[8], sv[8];
    const int w = threadIdx.x >> 5;
    if ((threadIdx.x & 31) == 0) { sm[w] = s; sv[w] = sq; }
    __syncthreads();
    if (threadIdx.x < 32) {
        s = (threadIdx.x < 8) ? sm[threadIdx.x] : 0.f;
        sq = (threadIdx.x < 8) ? sv[threadIdx.x] : 0.f;
#pragma unroll
        for (int o = 4; o; o >>= 1) {
            s += __shfl_xor_sync(0xffffffffu, s, o);
            sq += __shfl_xor_sync(0xffffffffu, sq, o);
        }
        if (threadIdx.x == 0) { sm[0] = s; sv[0] = sq; }
    }
    __syncthreads();
    const float mean = sm[0] * (1.f / DD);
    const float rstd = rsqrtf(sv[0] * (1.f / DD) - mean * mean + 1e-5f);
    const float4 g4 = *(const float4*)(g + c);
    const float4 b4 = *(const float4*)(bta + c);
    half2 h0 = __floats2half2_rn((v.x - mean) * rstd * g4.x + b4.x,
                                 (v.y - mean) * rstd * g4.y + b4.y);
    half2 h1 = __floats2half2_rn((v.z - mean) * rstd * g4.z + b4.z,
                                 (v.w - mean) * rstd * g4.w + b4.w);
    *(half2*)(out + row * DD + c) = h0;
    *(half2*)(out + row * DD + c + 2) = h1;
}

// ---------------------------------------------------------------------------
// LayerNorm generic (cond path, L=768)
// ---------------------------------------------------------------------------
template <int DIM>
__global__ void ln_kernel(const float* __restrict__ x, const float* __restrict__ g,
                          const float* __restrict__ bta, __half* __restrict__ out) {
    constexpr int PER = DIM / 256;
    const size_t row = blockIdx.x;
    const float* xr = x + row * DIM;
    float v[PER];
    float s = 0.f, sq = 0.f;
#pragma unroll
    for (int i = 0; i < PER; i++) {
        v[i] = xr[threadIdx.x + 256 * i];
        s += v[i];
        sq += v[i] * v[i];
    }
#pragma unroll
    for (int o = 16; o; o >>= 1) {
        s += __shfl_xor_sync(0xffffffffu, s, o);
        sq += __shfl_xor_sync(0xffffffffu, sq, o);
    }
    __shared__ float sm[8], sv[8];
    int w = threadIdx.x >> 5;
    if ((threadIdx.x & 31) == 0) { sm[w] = s; sv[w] = sq; }
    __syncthreads();
    if (threadIdx.x < 32) {
        s = (threadIdx.x < 8) ? sm[threadIdx.x] : 0.f;
        sq = (threadIdx.x < 8) ? sv[threadIdx.x] : 0.f;
#pragma unroll
        for (int o = 4; o; o >>= 1) {
            s += __shfl_xor_sync(0xffffffffu, s, o);
            sq += __shfl_xor_sync(0xffffffffu, sq, o);
        }
        if (threadIdx.x == 0) { sm[0] = s; sv[0] = sq; }
    }
    __syncthreads();
    const float mean = sm[0] * (1.f / DIM);
    const float var = sv[0] * (1.f / DIM) - mean * mean;
    const float rstd = rsqrtf(var + 1e-5f);
    __half* orow = out + row * DIM;
#pragma unroll
    for (int i = 0; i < PER; i++) {
        int c = threadIdx.x + 256 * i;
        orow[c] = __float2half_rn((v[i] - mean) * rstd * g[c] + bta[c]);
    }
}

// ---------------------------------------------------------------------------
// fp16 tensor-core GEMM: 128x128 tile, BK=64, cp.async 3-stage, f32 accum.
// 8 warps (2m x 4n), warp tile 64x32.  (R11/R12 proven config)
// FUSE_PV: tile == one (b,head): row softmax -> P(fp16, smem) -> P @ ctx -> y.
// OutT = __half: epilogue writes fp16 (kv path); OutT = float: f32 (y path).
// Dual (Bm2!=null): grid.x split between {Bm,bias,C} and {Bm2,bias2,C2}.
// ---------------------------------------------------------------------------
#define STAGES 3
#define AS_H 72              // halves per A smem row (64 + 8 pad)
#define BS_H 136             // halves per B smem row (128 + 8 pad)
#define A_ST_H (128 * AS_H)
#define B_ST_H (64 * BS_H)
#define SMEM_BYTES (STAGES * (A_ST_H + B_ST_H) * 2)   // 107520
#define P_OFF   8192
#define CTX_OFF (P_OFF + 128 * BS_H * 2)              // 43008
#define RED_OFF (CTX_OFF + 128 * BS_H * 2)            // 77824

template <bool FUSE_PV, typename OutT>
__global__ void __launch_bounds__(256, 2)
gemm_fp16(const __half* __restrict__ A, const __half* __restrict__ Bm,
          const float* __restrict__ bias, OutT* __restrict__ C,
          const __half* __restrict__ Bm2, const float* __restrict__ bias2,
          OutT* __restrict__ C2, const __half* __restrict__ ctxg,
          int K, int lda, int ldb, int ldc) {
    extern __shared__ __align__(16) char smraw[];
    __half* Asm = (__half*)smraw;
    __half* Bsm = Asm + STAGES * A_ST_H;

    int tN;
    if (Bm2 != nullptr) {
        const int half_g = gridDim.x >> 1;
        if (blockIdx.x >= half_g) {
            Bm = Bm2; bias = bias2; C = C2;
            tN = (blockIdx.x - half_g) * 128;
        } else {
            tN = blockIdx.x * 128;
        }
    } else {
        tN = blockIdx.x * 128;
    }
    const int tM = blockIdx.y * 128;
    const int tid = threadIdx.x;
    const int lane = tid & 31, warp = tid >> 5;
    const int m_base = (warp & 1) * 64;
    const int n_base = (warp >> 1) * 32;

    const __half* Ag = A + (size_t)tM * lda;
    const __half* Bg = Bm + tN;
    const int nk = K >> 6;   // BK = 64

    auto issue = [&](int kt) {
        const int st = kt % STAGES;
        __half* Al = Asm + st * A_ST_H;
        __half* Bl = Bsm + st * B_ST_H;
        const int k0 = kt << 6;
#pragma unroll
        for (int j = 0; j < 4; j++) {
            const int ci = tid + 256 * j;
            const int r = ci >> 3, c = (ci & 7) * 8;
            cp16(Al + r * AS_H + c, Ag + (size_t)r * lda + k0 + c);
        }
#pragma unroll
        for (int j = 0; j < 4; j++) {
            const int ci = tid + 256 * j;
            const int r = ci >> 4, c = (ci & 15) * 8;
            cp16(Bl + r * BS_H + c, Bg + (size_t)(k0 + r) * ldb + c);
        }
    };

    const uint32_t asm_u32 = (uint32_t)__cvta_generic_to_shared(Asm);
    const uint32_t bsm_u32 = (uint32_t)__cvta_generic_to_shared(Bsm);
    const uint32_t a_lane = (uint32_t)(((lane & 15) * AS_H + (lane >> 4) * 8) * 2);
    const uint32_t b_lane = (uint32_t)(((lane & 15) * BS_H + (lane >> 4) * 8) * 2);

    float acc[4][4][4];
#pragma unroll
    for (int i = 0; i < 4; i++)
#pragma unroll
        for (int j = 0; j < 4; j++)
#pragma unroll
            for (int r = 0; r < 4; r++) acc[i][j][r] = 0.f;

    issue(0);
    asm volatile("cp.async.commit_group;\n");
    issue(1);
    asm volatile("cp.async.commit_group;\n");

    for (int kt = 0; kt < nk; kt++) {
        asm volatile("cp.async.wait_group %0;\n" :: "n"(1));
        __syncthreads();
        if (kt + 2 < nk) issue(kt + 2);
        asm volatile("cp.async.commit_group;\n");

        const int st = kt % STAGES;
        const uint32_t a_st = asm_u32 + (uint32_t)(st * A_ST_H * 2) + a_lane;
        const uint32_t b_st = bsm_u32 + (uint32_t)(st * B_ST_H * 2) + b_lane;
#pragma unroll
        for (int kk = 0; kk < 4; kk++) {
            uint32_t af[4][4];
#pragma unroll
            for (int im = 0; im < 4; im++)
                ldsm4(af[im][0], af[im][1], af[im][2], af[im][3],
                      a_st + (uint32_t)(((m_base + im * 16) * AS_H + kk * 16) * 2));
            uint32_t bf[2][4];
#pragma unroll
            for (int t = 0; t < 2; t++)
                ldsm4t(bf[t][0], bf[t][1], bf[t][2], bf[t][3],
                       b_st + (uint32_t)((kk * 16 * BS_H + n_base + t * 16) * 2));
#pragma unroll
            for (int im = 0; im < 4; im++)
#pragma unroll
                for (int in = 0; in < 4; in++)
                    mma_fp16(acc[im][in], af[im], &bf[in >> 1][(in & 1) * 2]);
        }
    }
    __syncthreads();   // mainloop smem dead; epilogue may reuse

    // -------- bias --------
    float b0[4], b1[4];
#pragma unroll
    for (int in = 0; in < 4; in++) {
        if (bias != nullptr) {
            const int c = tN + n_base + in * 8 + 2 * (lane & 3);
            b0[in] = __ldg(bias + c);
            b1[in] = __ldg(bias + c + 1);
        } else { b0[in] = 0.f; b1[in] = 0.f; }
    }
#pragma unroll
    for (int im = 0; im < 4; im++)
#pragma unroll
        for (int in = 0; in < 4; in++) {
            acc[im][in][0] += b0[in];
            acc[im][in][1] += b1[in];
            acc[im][in][2] += b0[in];
            acc[im][in][3] += b1[in];
        }

    if (FUSE_PV) {
        // ---- start ctx loads (overlap with softmax math) ----
        __half* Psm = (__half*)(smraw + P_OFF);
        __half* Csm = (__half*)(smraw + CTX_OFF);
        float* red = (float*)(smraw + RED_OFF);
        float* red2 = red + 512;
        const int bh = (tM >> 12) * HH + blockIdx.x;
        const __half* cg = ctxg + ((size_t)bh << 14);
#pragma unroll
        for (int j = 0; j < 8; j++) {
            const int ci = tid + 256 * j;
            const int r = ci >> 4, c = (ci & 15) * 8;
            cp16(Csm + r * BS_H + c, cg + (size_t)r * HD + c);
        }
        asm volatile("cp.async.commit_group;\n");

        const int wn = warp >> 1;
        float m0[4], m1[4];
#pragma unroll
        for (int im = 0; im < 4; im++) {
            float a = -1e30f, b = -1e30f;
#pragma unroll
            for (int in = 0; in < 4; in++) {
                a = fmaxf(a, fmaxf(acc[im][in][0], acc[im][in][1]));
                b = fmaxf(b, fmaxf(acc[im][in][2], acc[im][in][3]));
            }
            a = fmaxf(a, __shfl_xor_sync(0xffffffffu, a, 1));
            a = fmaxf(a, __shfl_xor_sync(0xffffffffu, a, 2));
            b = fmaxf(b, __shfl_xor_sync(0xffffffffu, b, 1));
            b = fmaxf(b, __shfl_xor_sync(0xffffffffu, b, 2));
            m0[im] = a; m1[im] = b;
        }
        if ((lane & 3) == 0) {
#pragma unroll
            for (int im = 0; im < 4; im++) {
                const int r = m_base + im * 16 + (lane >> 2);
                red[r * 4 + wn] = m0[im];
                red[(r + 8) * 4 + wn] = m1[im];
            }
        }
        __syncthreads();
        float M0[4], M1[4];
#pragma unroll
        for (int im = 0; im < 4; im++) {
            const int r = m_base + im * 16 + (lane >> 2);
            M0[im] = fmaxf(fmaxf(red[r * 4], red[r * 4 + 1]),
                           fmaxf(red[r * 4 + 2], red[r * 4 + 3]));
            M1[im] = fmaxf(fmaxf(red[(r + 8) * 4], red[(r + 8) * 4 + 1]),
                           fmaxf(red[(r + 8) * 4 + 2], red[(r + 8) * 4 + 3]));
        }
        float s0[4], s1[4];
#pragma unroll
        for (int im = 0; im < 4; im++) {
            float sa = 0.f, sb = 0.f;
#pragma unroll
            for (int in = 0; in < 4; in++) {
                acc[im][in][0] = __expf(acc[im][in][0] - M0[im]);
                acc[im][in][1] = __expf(acc[im][in][1] - M0[im]);
                acc[im][in][2] = __expf(acc[im][in][2] - M1[im]);
                acc[im][in][3] = __expf(acc[im][in][3] - M1[im]);
                sa += acc[im][in][0] + acc[im][in][1];
                sb += acc[im][in][2] + acc[im][in][3];
            }
            sa += __shfl_xor_sync(0xffffffffu, sa, 1);
            sa += __shfl_xor_sync(0xffffffffu, sa, 2);
            sb += __shfl_xor_sync(0xffffffffu, sb, 1);
            sb += __shfl_xor_sync(0xffffffffu, sb, 2);
            s0[im] = sa; s1[im] = sb;
        }
        if ((lane & 3) == 0) {
#pragma unroll
            for (int im = 0; im < 4; im++) {
                const int r = m_base + im * 16 + (lane >> 2);
                red2[r * 4 + wn] = s0[im];
                red2[(r + 8) * 4 + wn] = s1[im];
            }
        }
        __syncthreads();
#pragma unroll
        for (int im = 0; im < 4; im++) {
            const int r = m_base + im * 16 + (lane >> 2);
            const float inv0 = 1.f / (red2[r * 4] + red2[r * 4 + 1] +
                                      red2[r * 4 + 2] + red2[r * 4 + 3]);
            const float inv1 = 1.f / (red2[(r + 8) * 4] + red2[(r + 8) * 4 + 1] +
                                      red2[(r + 8) * 4 + 2] + red2[(r + 8) * 4 + 3]);
#pragma unroll
            for (int in = 0; in < 4; in++) {
                const int c = n_base + in * 8 + 2 * (lane & 3);
                *(half2*)(Psm + (size_t)r * BS_H + c) =
                    __floats2half2_rn(acc[im][in][0] * inv0, acc[im][in][1] * inv0);
                *(half2*)(Psm + (size_t)(r + 8) * BS_H + c) =
                    __floats2half2_rn(acc[im][in][2] * inv1, acc[im][in][3] * inv1);
            }
        }
        asm volatile("cp.async.wait_group 0;\n");
        __syncthreads();

        float ac2[4][4][4];
#pragma unroll
        for (int i = 0; i < 4; i++)
#pragma unroll
            for (int j = 0; j < 4; j++)
#pragma unroll
                for (int r = 0; r < 4; r++) ac2[i][j][r] = 0.f;

        const uint32_t p_u32 = (uint32_t)__cvta_generic_to_shared(Psm) + b_lane;
        const uint32_t c_u32 = (uint32_t)__cvta_generic_to_shared(Csm) + b_lane;
#pragma unroll
        for (int kk = 0; kk < 8; kk++) {
            uint32_t af[4][4];
#pragma unroll
            for (int im = 0; im < 4; im++)
                ldsm4(af[im][0], af[im][1], af[im][2], af[im][3],
                      p_u32 + (uint32_t)(((m_base + im * 16) * BS_H + kk * 16) * 2));
            uint32_t bf[2][4];
#pragma unroll
            for (int t = 0; t < 2; t++)
                ldsm4t(bf[t][0], bf[t][1], bf[t][2], bf[t][3],
                       c_u32 + (uint32_t)((kk * 16 * BS_H + n_base + t * 16) * 2));
#pragma unroll
            for (int im = 0; im < 4; im++)
#pragma unroll
                for (int in = 0; in < 4; in++)
                    mma_fp16(ac2[im][in], af[im], &bf[in >> 1][(in & 1) * 2]);
        }
#pragma unroll
        for (int im = 0; im < 4; im++) {
            const int r0 = tM + m_base + im * 16 + (lane >> 2);
#pragma unroll
            for (int in = 0; in < 4; in++) {
                const int c = tN + n_base + in * 8 + 2 * (lane & 3);
                *(float2*)((float*)C + (size_t)r0 * ldc + c) =
                    make_float2(ac2[im][in][0], ac2[im][in][1]);
                *(float2*)((float*)C + (size_t)(r0 + 8) * ldc + c) =
                    make_float2(ac2[im][in][2], ac2[im][in][3]);
            }
        }
    } else {
#pragma unroll
        for (int im = 0; im < 4; im++) {
            const int r0 = tM + m_base + im * 16 + (lane >> 2);
#pragma unroll
            for (int in = 0; in < 4; in++) {
                const int c = tN + n_base + in * 8 + 2 * (lane & 3);
                if constexpr (sizeof(OutT) == 2) {
                    *(half2*)((__half*)C + (size_t)r0 * ldc + c) =
                        __floats2half2_rn(acc[im][in][0], acc[im][in][1]);
                    *(half2*)((__half*)C + (size_t)(r0 + 8) * ldc + c) =
                        __floats2half2_rn(acc[im][in][2], acc[im][in][3]);
                } else {
                    *(float2*)((float*)C + (size_t)r0 * ldc + c) =
                        make_float2(acc[im][in][0], acc[im][in][1]);
                    *(float2*)((float*)C + (size_t)(r0 + 8) * ldc + c) =
                        make_float2(acc[im][in][2], acc[im][in][3]);
                }
            }
        }
    }
}

// ---------------------------------------------------------------------------
// context partials with ONLINE split-softmax (no global k stats needed):
// each CTA (bh, 64-token split) computes its LOCAL per-column (m_p, s_p) from
// registers, Ek = exp(k - m_p), cp_p = Ek^T @ V (UNNORMALIZED, fp16),
// and stores (m_p, s_p) for the rescaling reduce.
// Thread t's half2 column index (tid & 63) is invariant across its 16 rows.
// ---------------------------------------------------------------------------
__global__ void __launch_bounds__(256)
context_mma(const __half* __restrict__ k, const __half* __restrict__ v,
            __half* __restrict__ cp, float* __restrict__ pm,
            float* __restrict__ ps) {
    const int bh = blockIdx.x;
    const int b = bh >> 3, h = bh & 7;
    const int split = blockIdx.y;
    const int n0 = split * 64;
    __shared__ __half Ek[64 * BS_H], Vs[64 * BS_H];
    __shared__ float sred[128][4];
    __shared__ float colM[128];

    const __half* kb = k + (size_t)b * NN * DD + h * HD;
    const __half* vb = v + (size_t)b * NN * DD + h * HD;

    const int tid = threadIdx.x;
    const int lane = tid & 31, warp = tid >> 5;
    const int m_base = (warp & 1) * 64;
    const int n_base = (warp >> 1) * 32;

    // pass 1: load k (regs) + v (smem); local max for this thread's 2 cols
    const int c0 = (tid & 63) * 2;
    const int slot = tid >> 6;               // 0..3
    half2 kreg[16];
    float lm0 = -1e30f, lm1 = -1e30f;
#pragma unroll
    for (int i = 0; i < 16; i++) {
        const int r = slot + 4 * i;
        const size_t gi = (size_t)(n0 + r) * DD + c0;
        kreg[i] = *(const half2*)(kb + gi);
        *(half2*)(Vs + r * BS_H + c0) = *(const half2*)(vb + gi);
        lm0 = fmaxf(lm0, __half2float(kreg[i].x));
        lm1 = fmaxf(lm1, __half2float(kreg[i].y));
    }
    sred[c0][slot] = lm0;
    sred[c0 + 1][slot] = lm1;
    __syncthreads();
    if (tid < 128)
        colM[tid] = fmaxf(fmaxf(sred[tid][0], sred[tid][1]),
                          fmaxf(sred[tid][2], sred[tid][3]));
    __syncthreads();

    // pass 2: Ek = exp(k - m_loc), local sums
    const float M0 = colM[c0], M1 = colM[c0 + 1];
    float ls0 = 0.f, ls1 = 0.f;
#pragma unroll
    for (int i = 0; i < 16; i++) {
        const int r = slot + 4 * i;
        const float e0 = __expf(__half2float(kreg[i].x) - M0);
        const float e1 = __expf(__half2float(kreg[i].y) - M1);
        *(half2*)(Ek + r * BS_H + c0) = __floats2half2_rn(e0, e1);
        ls0 += e0;
        ls1 += e1;
    }
    sred[c0][slot] = ls0;
    sred[c0 + 1][slot] = ls1;
    __syncthreads();                         // also publishes Ek/Vs
    if (tid < 128) {
        const size_t si = ((size_t)(split * 32 + bh) << 7) + tid;
        pm[si] = colM[tid];
        ps[si] = sred[tid][0] + sred[tid][1] + sred[tid][2] + sred[tid][3];
    }

    float acc[4][4][4];
#pragma unroll
    for (int i = 0; i < 4; i++)
#pragma unroll
        for (int j = 0; j < 4; j++)
#pragma unroll
            for (int r = 0; r < 4; r++) acc[i][j][r] = 0.f;

    const uint32_t lane_off = (uint32_t)(((lane & 15) * BS_H + (lane >> 4) * 8) * 2);
    const uint32_t e_u32 = (uint32_t)__cvta_generic_to_shared(Ek) + lane_off;
    const uint32_t v_u32 = (uint32_t)__cvta_generic_to_shared(Vs) + lane_off;
#pragma unroll
    for (int kk = 0; kk < 4; kk++) {
        uint32_t af[4][4];
#pragma unroll
        for (int im = 0; im < 4; im++) {
            uint32_t r0, r1, r2, r3;
            ldsm4t(r0, r1, r2, r3,
                   e_u32 + (uint32_t)((kk * 16 * BS_H + m_base + im * 16) * 2));
            af[im][0] = r0; af[im][1] = r2; af[im][2] = r1; af[im][3] = r3;
        }
        uint32_t bf[2][4];
#pragma unroll
        for (int t = 0; t < 2; t++)
            ldsm4t(bf[t][0], bf[t][1], bf[t][2], bf[t][3],
                   v_u32 + (uint32_t)((kk * 16 * BS_H + n_base + t * 16) * 2));
#pragma unroll
        for (int im = 0; im < 4; im++)
#pragma unroll
            for (int in = 0; in < 4; in++)
                mma_fp16(acc[im][in], af[im], &bf[in >> 1][(in & 1) * 2]);
    }

    __half* out = cp + ((size_t)(split * 32 + bh)) * (HD * HD);
#pragma unroll
    for (int im = 0; im < 4; im++) {
        const int r = m_base + im * 16 + (lane >> 2);
#pragma unroll
        for (int in = 0; in < 4; in++) {
            const int c = n_base + in * 8 + 2 * (lane & 3);
            *(half2*)(out + (size_t)r * HD + c) =
                __floats2half2_rn(acc[im][in][0], acc[im][in][1]);
            *(half2*)(out + (size_t)(r + 8) * HD + c) =
                __floats2half2_rn(acc[im][in][2], acc[im][in][3]);
        }
    }
}

// ---------------------------------------------------------------------------
// rescaling reduce over NSPLIT partials:
//   M = max_p m_p ; S = sum_p s_p e^{m_p-M} ; ctx = sum_p e^{m_p-M} cp_p / S
// pm/ps indices are warp-uniform (i>>7 constant per 32 lanes) -> broadcast.
// ---------------------------------------------------------------------------
__global__ void ctx_reduce(const __half* __restrict__ cp,
                           const float* __restrict__ pm,
                           const float* __restrict__ ps,
                           __half* __restrict__ ctx) {
    const size_t i = (size_t)blockIdx.x * 256 + threadIdx.x;
    const int bhdk = (int)(i >> 7);           // (bh << 7) + dk
    const int bh = bhdk >> 7, dk = bhdk & 127;

    float mm[NSPLIT];
    float M = -1e30f;
#pragma unroll
    for (int p = 0; p < NSPLIT; p++) {
        mm[p] = pm[((size_t)(p * 32 + bh) << 7) + dk];
        M = fmaxf(M, mm[p]);
    }
    float S = 0.f, a = 0.f;
#pragma unroll
    for (int p = 0; p < NSPLIT; p++) {
        const float w = __expf(mm[p] - M);
        S += ps[((size_t)(p * 32 + bh) << 7) + dk] * w;
        a += __half2float(cp[i + (size_t)p * 524288]) * w;
    }
    ctx[i] = __float2half_rn(a / S);
}

// ---------------------------------------------------------------------------
// Launch
// ---------------------------------------------------------------------------
extern "C" void kernel_launch(void* const* d_in, const int* in_sizes, int n_in,
                              void* d_out, int out_size) {
    const float* x     = (const float*)d_in[0];
    const float* cond  = (const float*)d_in[1];
    const float* ln_g  = (const float*)d_in[2];
    const float* ln_b  = (const float*)d_in[3];
    const float* tln_g = (const float*)d_in[4];
    const float* tln_b = (const float*)d_in[5];
    const float* Wq    = (const float*)d_in[6];
    const float* bq    = (const float*)d_in[7];
    const float* Wk    = (const float*)d_in[8];
    const float* bk    = (const float*)d_in[9];
    const float* Wv    = (const float*)d_in[10];
    const float* bv    = (const float*)d_in[11];
    float* y = (float*)d_out;

    float* base = nullptr;
    cudaGetSymbolAddress((void**)&base, g_buf);
    __half* xn   = (__half*)(base + OFF_XN);
    __half* cn   = (__half*)(base + OFF_CN);
    __half* kk   = (__half*)(base + OFF_K);
    __half* vv   = (__half*)(base + OFF_V);
    float*  pm   = base + OFF_PM;
    float*  ps   = base + OFF_PS;
    __half* cp   = (__half*)(base + OFF_CP);
    __half* ctx  = (__half*)(base + OFF_CTX);
    __half* wq16 = (__half*)(base + OFF_WQ16);
    __half* wk16 = (__half*)(base + OFF_WK16);
    __half* wv16 = (__half*)(base + OFF_WV16);

    cudaFuncSetAttribute(gemm_fp16<true, float>,
                         cudaFuncAttributeMaxDynamicSharedMemorySize, SMEM_BYTES);
    cudaFuncSetAttribute(gemm_fp16<false, __half>,
                         cudaFuncAttributeMaxDynamicSharedMemorySize, SMEM_BYTES);

    // 0: convert weights to fp16; LN(cond)
    conv_weights<<<2560, 256>>>(Wq, Wk, Wv, wq16);
    ln_kernel<LL><<<BB * NN, 256>>>(cond, tln_g, tln_b, cn);

    // 1: k,v = cn @ W{k,v} + b fused in one launch (fp16 outputs)
    gemm_fp16<false, __half><<<dim3(2 * DD / 128, (BB * NN) / 128, 1), 256, SMEM_BYTES>>>(
        cn, wk16, bk, kk, wv16, bv, vv, nullptr,
        LL, LL, DD, DD);

    // 2-3: context via online split-softmax (local stats; no kcol_stats kernel)
    context_mma<<<dim3(BB * HH, NSPLIT), 256>>>(kk, vv, cp, pm, ps);
    ctx_reduce<<<(BB * HH * HD * HD) / 256, 256>>>(cp, pm, ps, ctx);

    // 4: LN(x) (vectorized, fp16 output)
    ln1024<<<BB * TT, 256>>>(x, ln_g, ln_b, xn);

    // 5: FUSED: q = softmax_head(xn @ Wq + bq); y = q @ ctx  -> d_out (f32)
    gemm_fp16<true, float><<<dim3(DD / 128, (BB * TT) / 128, 1), 256, SMEM_BYTES>>>(
        xn, wq16, bq, y, nullptr, nullptr, nullptr, ctx,
        DD, DD, DD, DD);
}